// round 1
// baseline (speedup 1.0000x reference)
#include <cuda_runtime.h>
#include <cstddef>

// ---------------------------------------------------------------------------
// VQ-VAE 1D forward. All intermediates in __device__ globals (no allocation).
// Buffers sized for the largest intermediate: 16*64*1024 == 16*32*2048 floats.
// ---------------------------------------------------------------------------
#define DEVBUF_N (16 * 64 * 1024)
__device__ float g_A[DEVBUF_N];
__device__ float g_B[DEVBUF_N];
__device__ float g_C[DEVBUF_N];
__device__ float g_enorm[512];

// ---------------------------------------------------------------------------
// Heavy first conv: 768->32, k=4, stride=2, pad=1, +bias, +ReLU
// x: (16,768,4096) -> out: (16,32,2048)
// Block: 128 threads, tile = 64 output positions x all 32 oc for one batch.
// Each thread: 4 oc x 4 t accumulators. Input channels processed in chunks
// of 32 staged through shared memory together with the matching weights.
// ---------------------------------------------------------------------------
__global__ __launch_bounds__(128) void conv_first(
    const float* __restrict__ x, const float* __restrict__ w,
    const float* __restrict__ bias, float* __restrict__ out)
{
    const int b  = blockIdx.y;
    const int t0 = blockIdx.x * 64;
    const int tid = threadIdx.x;
    const int tg  = tid & 15;   // 16 t-groups; t_local = tg + 16*j
    const int ocg = tid >> 4;   // 8 oc-groups; oc = ocg*4 + m

    __shared__ float xs[32 * 132];                 // [ic][pos], 130 used
    __shared__ __align__(16) float ws[32 * 128];   // [ic][oc*4+k]

    float acc[4][4] = {};

    for (int c0 = 0; c0 < 768; c0 += 32) {
        __syncthreads();
        // stage x chunk: positions 2*t0-1 .. 2*t0+128 (130 values), zero-padded
        for (int i = tid; i < 32 * 130; i += 128) {
            int ic = i / 130;
            int p  = i - ic * 130;
            int pos = t0 * 2 - 1 + p;
            float v = (pos >= 0 && pos < 4096)
                          ? x[((size_t)b * 768 + c0 + ic) * 4096 + pos] : 0.f;
            xs[ic * 132 + p] = v;
        }
        // stage weights: w[oc][c0+ic][k] -> ws[ic][oc*4+k]
        for (int i = tid; i < 32 * 128; i += 128) {
            int oc = i >> 7;
            int r  = i & 127;                       // ic*4 + k
            ws[(r >> 2) * 128 + oc * 4 + (r & 3)] = w[oc * 3072 + c0 * 4 + r];
        }
        __syncthreads();

        #pragma unroll 4
        for (int ic = 0; ic < 32; ic++) {
            float4 wv[4];
            #pragma unroll
            for (int m = 0; m < 4; m++)
                wv[m] = *(const float4*)&ws[ic * 128 + (ocg * 4 + m) * 4];
            #pragma unroll
            for (int j = 0; j < 4; j++) {
                int base = ic * 132 + 2 * (tg + 16 * j);
                float a0 = xs[base], a1 = xs[base + 1];
                float a2 = xs[base + 2], a3 = xs[base + 3];
                #pragma unroll
                for (int m = 0; m < 4; m++) {
                    acc[m][j] = fmaf(wv[m].x, a0, acc[m][j]);
                    acc[m][j] = fmaf(wv[m].y, a1, acc[m][j]);
                    acc[m][j] = fmaf(wv[m].z, a2, acc[m][j]);
                    acc[m][j] = fmaf(wv[m].w, a3, acc[m][j]);
                }
            }
        }
    }

    #pragma unroll
    for (int m = 0; m < 4; m++) {
        int oc = ocg * 4 + m;
        float bv = bias[oc];
        #pragma unroll
        for (int j = 0; j < 4; j++) {
            int t = t0 + tg + 16 * j;
            out[((size_t)b * 32 + oc) * 2048 + t] = fmaxf(acc[m][j] + bv, 0.f);
        }
    }
}

// ---------------------------------------------------------------------------
// Generic small conv: CIN,COUT <= 64, kernel K, stride S, pad P.
// Flags: PRE (relu on loaded input), POST (relu on output),
//        RES (out = conv + res), BIAS.
// Tile: 64 outputs x all COUT channels per block. NT = COUT*4 threads,
// each thread 4 oc x 4 t accumulators. Weights + input tile in dyn smem.
// ---------------------------------------------------------------------------
template <int CIN, int COUT, int K, int S, int P,
          bool PRE, bool POST, bool RES, bool BIAS>
__global__ __launch_bounds__(COUT * 4) void convk(
    const float* __restrict__ in, const float* __restrict__ w,
    const float* __restrict__ bias, const float* __restrict__ res,
    float* __restrict__ out, int Lin, int Lout)
{
    constexpr int TT = 64;
    constexpr int XW = S * TT + K - 1;
    constexpr int XWP = XW + 1;
    constexpr int NT = COUT * 4;

    extern __shared__ float sm[];
    float* ws = sm;                  // [ic][oc][k]
    float* xs = sm + CIN * COUT * K; // [ic][XWP]

    const int tid = threadIdx.x;
    const int b   = blockIdx.y;
    const int t0  = blockIdx.x * TT;
    const int p0  = t0 * S - P;

    for (int i = tid; i < CIN * COUT * K; i += NT) {
        int oc = i / (CIN * K);
        int r  = i - oc * (CIN * K);
        int ic = r / K;
        int k  = r - ic * K;
        ws[(ic * COUT + oc) * K + k] = w[i];
    }
    for (int i = tid; i < CIN * XW; i += NT) {
        int ic = i / XW;
        int l  = i - ic * XW;
        int pos = p0 + l;
        float v = (pos >= 0 && pos < Lin)
                      ? in[((size_t)b * CIN + ic) * Lin + pos] : 0.f;
        if (PRE) v = fmaxf(v, 0.f);
        xs[ic * XWP + l] = v;
    }
    __syncthreads();

    const int tg  = tid & 15;
    const int ocg = tid >> 4;
    float acc[4][4] = {};

    #pragma unroll 4
    for (int ic = 0; ic < CIN; ic++) {
        float wk[4][K];
        #pragma unroll
        for (int m = 0; m < 4; m++)
            #pragma unroll
            for (int k = 0; k < K; k++)
                wk[m][k] = ws[(ic * COUT + ocg * 4 + m) * K + k];
        #pragma unroll
        for (int j = 0; j < 4; j++) {
            const float* xp = &xs[ic * XWP + S * (tg + 16 * j)];
            float xv[K];
            #pragma unroll
            for (int k = 0; k < K; k++) xv[k] = xp[k];
            #pragma unroll
            for (int m = 0; m < 4; m++)
                #pragma unroll
                for (int k = 0; k < K; k++)
                    acc[m][j] = fmaf(wk[m][k], xv[k], acc[m][j]);
        }
    }

    #pragma unroll
    for (int m = 0; m < 4; m++) {
        int oc = ocg * 4 + m;
        float bv = 0.f;
        if (BIAS) bv = bias[oc];
        #pragma unroll
        for (int j = 0; j < 4; j++) {
            int t = t0 + tg + 16 * j;
            size_t oi = ((size_t)b * COUT + oc) * Lout + t;
            float v = acc[m][j] + bv;
            if (RES) v += res[oi];
            if (POST) v = fmaxf(v, 0.f);
            out[oi] = v;
        }
    }
}

// ---------------------------------------------------------------------------
// ConvTranspose1d: k=4, stride=2, pad=1. Each output uses 2 taps:
//   out[oc][t] = b[oc] + sum_ic sum_{k: (t+1-k) even, idx in range}
//                w[ic][oc][k] * in[ic][(t+1-k)/2]
// Weight layout (torch ConvTranspose1d): (CIN, COUT, 4) — copied linearly.
// Tile = 64 outputs; input tile = CIN x 34 positions.
// ---------------------------------------------------------------------------
template <int CIN, int COUT, bool PRE, bool POST>
__global__ __launch_bounds__(COUT * 4) void tconv(
    const float* __restrict__ in, const float* __restrict__ w,
    const float* __restrict__ bias, float* __restrict__ out,
    int Lin, int Lout)
{
    constexpr int NT = COUT * 4;
    __shared__ __align__(16) float ws[CIN * COUT * 4];
    __shared__ float xs[CIN * 35];

    const int tid = threadIdx.x;
    const int b   = blockIdx.y;
    const int t0  = blockIdx.x * 64;
    const int xbase = (t0 >> 1) - 1;

    for (int i = tid; i < CIN * COUT * 4; i += NT) ws[i] = w[i];
    for (int i = tid; i < CIN * 34; i += NT) {
        int ic = i / 34;
        int l  = i - ic * 34;
        int pos = xbase + l;
        float v = (pos >= 0 && pos < Lin)
                      ? in[((size_t)b * CIN + ic) * Lin + pos] : 0.f;
        if (PRE) v = fmaxf(v, 0.f);
        xs[ic * 35 + l] = v;
    }
    __syncthreads();

    const int tg  = tid & 15;
    const int ocg = tid >> 4;
    float acc[4][4] = {};

    #pragma unroll 4
    for (int ic = 0; ic < CIN; ic++) {
        float wk[4][4];
        #pragma unroll
        for (int m = 0; m < 4; m++) {
            float4 f = ((const float4*)ws)[ic * COUT + ocg * 4 + m];
            wk[m][0] = f.x; wk[m][1] = f.y; wk[m][2] = f.z; wk[m][3] = f.w;
        }
        #pragma unroll
        for (int j = 0; j < 4; j++) {
            int tl = tg + 16 * j;
            #pragma unroll
            for (int k = 0; k < 4; k++) {
                int e = tl + 1 - k;
                if (!(e & 1)) {
                    float xv = xs[ic * 35 + (e >> 1) + 1];
                    #pragma unroll
                    for (int m = 0; m < 4; m++)
                        acc[m][j] = fmaf(wk[m][k], xv, acc[m][j]);
                }
            }
        }
    }

    #pragma unroll
    for (int m = 0; m < 4; m++) {
        int oc = ocg * 4 + m;
        float bv = bias[oc];
        #pragma unroll
        for (int j = 0; j < 4; j++) {
            int t = t0 + tg + 16 * j;
            float v = acc[m][j] + bv;
            if (POST) v = fmaxf(v, 0.f);
            out[((size_t)b * COUT + oc) * Lout + t] = v;
        }
    }
}

// ---------------------------------------------------------------------------
// Codebook squared norms: enorm[c] = sum_d emb[c][d]^2
// ---------------------------------------------------------------------------
__global__ void enorm_kernel(const float* __restrict__ emb, float* __restrict__ en)
{
    int i = blockIdx.x * blockDim.x + threadIdx.x;
    if (i < 512) {
        float s = 0.f;
        #pragma unroll
        for (int d = 0; d < 64; d++) {
            float v = emb[i * 64 + d];
            s = fmaf(v, v, s);
        }
        en[i] = s;
    }
}

// ---------------------------------------------------------------------------
// VQ: for each vector z[b,:,t] (64 dims) find argmin_c (enorm[c] - 2 z.e_c)
// (identical ordering to ref's ||x||^2+||e||^2-2x.e), first-min tie rule,
// then q[b,:,t] = emb[argmin]. One thread per vector; codebook streamed
// through shared memory in chunks of 64 codes; vector held in registers.
// ---------------------------------------------------------------------------
__global__ __launch_bounds__(128) void vq_kernel(
    const float* __restrict__ z, const float* __restrict__ emb,
    const float* __restrict__ enorm, float* __restrict__ q)
{
    const int b = blockIdx.y;
    const int t = blockIdx.x * 128 + threadIdx.x;

    float4 v[16];
    #pragma unroll
    for (int d = 0; d < 16; d++) {
        v[d].x = z[((size_t)b * 64 + 4 * d + 0) * 1024 + t];
        v[d].y = z[((size_t)b * 64 + 4 * d + 1) * 1024 + t];
        v[d].z = z[((size_t)b * 64 + 4 * d + 2) * 1024 + t];
        v[d].w = z[((size_t)b * 64 + 4 * d + 3) * 1024 + t];
    }

    __shared__ __align__(16) float es[64 * 64];
    float best = 3.4e38f;
    int bi = 0;

    for (int c0 = 0; c0 < 512; c0 += 64) {
        __syncthreads();
        for (int i = threadIdx.x; i < 64 * 64; i += 128)
            es[i] = emb[c0 * 64 + i];
        __syncthreads();
        for (int c = 0; c < 64; c++) {
            const float4* e4 = (const float4*)&es[c * 64];
            float s0 = 0.f, s1 = 0.f, s2 = 0.f, s3 = 0.f;
            #pragma unroll
            for (int d = 0; d < 16; d++) {
                float4 e = e4[d];
                s0 = fmaf(v[d].x, e.x, s0);
                s1 = fmaf(v[d].y, e.y, s1);
                s2 = fmaf(v[d].z, e.z, s2);
                s3 = fmaf(v[d].w, e.w, s3);
            }
            float dist = enorm[c0 + c] - 2.f * ((s0 + s1) + (s2 + s3));
            if (dist < best) { best = dist; bi = c0 + c; }
        }
    }

    #pragma unroll 8
    for (int d = 0; d < 64; d++)
        q[((size_t)b * 64 + d) * 1024 + t] = __ldg(&emb[bi * 64 + d]);
}

// ---------------------------------------------------------------------------
// Host-side launch helpers
// ---------------------------------------------------------------------------
template <int CIN, int COUT, int K, int S, int P,
          bool PRE, bool POST, bool RES, bool BIAS>
static void launch_convk(const float* in, const float* w, const float* bias,
                         const float* res, float* out, int Lin, int Lout)
{
    constexpr int TT = 64;
    constexpr int XW = S * TT + K - 1;
    constexpr int XWP = XW + 1;
    constexpr int NT = COUT * 4;
    size_t smem = (size_t)(CIN * COUT * K + CIN * XWP) * sizeof(float);
    auto kern = convk<CIN, COUT, K, S, P, PRE, POST, RES, BIAS>;
    cudaFuncSetAttribute(kern, cudaFuncAttributeMaxDynamicSharedMemorySize,
                         (int)smem);
    kern<<<dim3(Lout / TT, 16), NT, smem>>>(in, w, bias, res, out, Lin, Lout);
}

extern "C" void kernel_launch(void* const* d_in, const int* in_sizes, int n_in,
                              void* d_out, int out_size)
{
    (void)in_sizes; (void)n_in; (void)out_size;

    const float* x       = (const float*)d_in[0];
    const float* enc_w1  = (const float*)d_in[1];
    const float* enc_b1  = (const float*)d_in[2];
    const float* enc_w2  = (const float*)d_in[3];
    const float* enc_b2  = (const float*)d_in[4];
    const float* enc_w3  = (const float*)d_in[5];
    const float* enc_b3  = (const float*)d_in[6];
    const float* e_r0w1  = (const float*)d_in[7];
    const float* e_r0w2  = (const float*)d_in[8];
    const float* e_r1w1  = (const float*)d_in[9];
    const float* e_r1w2  = (const float*)d_in[10];
    const float* prevq_w = (const float*)d_in[11];
    const float* prevq_b = (const float*)d_in[12];
    const float* emb     = (const float*)d_in[13];
    const float* dec_w1  = (const float*)d_in[14];
    const float* dec_b1  = (const float*)d_in[15];
    const float* d_r0w1  = (const float*)d_in[16];
    const float* d_r0w2  = (const float*)d_in[17];
    const float* d_r1w1  = (const float*)d_in[18];
    const float* d_r1w2  = (const float*)d_in[19];
    const float* dect1_w = (const float*)d_in[20];
    const float* dect1_b = (const float*)d_in[21];
    const float* dect2_w = (const float*)d_in[22];
    const float* dect2_b = (const float*)d_in[23];
    float* out = (float*)d_out;

    float *A, *B, *C, *EN;
    cudaGetSymbolAddress((void**)&A,  g_A);
    cudaGetSymbolAddress((void**)&B,  g_B);
    cudaGetSymbolAddress((void**)&C,  g_C);
    cudaGetSymbolAddress((void**)&EN, g_enorm);

    // Encoder
    conv_first<<<dim3(32, 16), 128>>>(x, enc_w1, enc_b1, A);            // A:(16,32,2048) relu
    launch_convk<32, 64, 4, 2, 1, false, true,  false, true >(A, enc_w2, enc_b2, nullptr, B, 2048, 1024); // B relu
    launch_convk<64, 64, 3, 1, 1, false, false, false, true >(B, enc_w3, enc_b3, nullptr, C, 1024, 1024); // C
    // Encoder residual stack
    launch_convk<64, 32, 3, 1, 1, true,  false, false, false>(C, e_r0w1, nullptr, nullptr, A, 1024, 1024);
    launch_convk<32, 64, 1, 1, 0, true,  false, true,  false>(A, e_r0w2, nullptr, C,       B, 1024, 1024);
    launch_convk<64, 32, 3, 1, 1, true,  false, false, false>(B, e_r1w1, nullptr, nullptr, A, 1024, 1024);
    launch_convk<32, 64, 1, 1, 0, true,  false, true,  false>(A, e_r1w2, nullptr, B,       C, 1024, 1024);
    // pre-VQ 1x1 (stack's trailing relu folded into PRE)
    launch_convk<64, 64, 1, 1, 0, true,  false, false, true >(C, prevq_w, prevq_b, nullptr, B, 1024, 1024); // B = z
    // VQ
    enorm_kernel<<<1, 512>>>(emb, EN);
    vq_kernel<<<dim3(8, 16), 128>>>(B, emb, EN, A);                      // A = q
    // Decoder
    launch_convk<64, 64, 3, 1, 1, false, false, false, true >(A, dec_w1, dec_b1, nullptr, B, 1024, 1024);
    launch_convk<64, 32, 3, 1, 1, true,  false, false, false>(B, d_r0w1, nullptr, nullptr, C, 1024, 1024);
    launch_convk<32, 64, 1, 1, 0, true,  false, true,  false>(C, d_r0w2, nullptr, B,       A, 1024, 1024);
    launch_convk<64, 32, 3, 1, 1, true,  false, false, false>(A, d_r1w1, nullptr, nullptr, C, 1024, 1024);
    launch_convk<32, 64, 1, 1, 0, true,  false, true,  false>(C, d_r1w2, nullptr, A,       B, 1024, 1024);
    // Transposed convs (stack's trailing relu folded into PRE of dect1)
    tconv<64, 32, true,  true ><<<dim3(32, 16), 128>>>(B, dect1_w, dect1_b, C,   1024, 2048); // C relu
    tconv<32, 64, false, false><<<dim3(64, 16), 256>>>(C, dect2_w, dect2_b, out, 2048, 4096); // final
}